// round 11
// baseline (speedup 1.0000x reference)
#include <cuda_runtime.h>
#include <cuda_fp16.h>
#include <cstdint>

#define M_KW 512
#define K_D  768
#define T_DIM 512
#define V_SZ 49408
#define NTILE (V_SZ / 128)         // 386
#define EPSF 1e-8f

// pass-1 GEMM tiling (R5 shape, fp16 accumulate)
#define BM 128
#define BN 128
#define BK 32
#define NKT (T_DIM / BK)           // 16
#define NSTAGE 4
#define A_STG (BM * 64)
#define B_STG (BN * 64)
#define STG_BYTES (A_STG + B_STG)  // 16384
#define DSMEM (NSTAGE * STG_BYTES + 1024)

#define PROJ_BLKS 64               // 64x64 proj tiles (proven 34.3us)

// ---------------- device scratch ------------------------------------------------
__device__ float g_kw[M_KW * T_DIM];                       // fp32 projected keywords
__device__ __half g_A16[M_KW * T_DIM];                     // fp16 of g_kw
__device__ __half g_B16[(size_t)V_SZ * T_DIM];             // fp16 normalized emb
__device__ float g_invn[V_SZ];                             // 1/max(||emb_v||,eps)
__device__ __half g_s16[(size_t)M_KW * V_SZ];              // fp16 scores (50 MB)
__device__ float g_tilemax[(size_t)M_KW * NTILE];          // per-row per-tile max
__device__ unsigned g_hikey[M_KW];                         // fkey(max fp16 score)
__device__ unsigned long long g_best[M_KW];                // packed exact argmax

// ---------------- helpers -------------------------------------------------------
__device__ __forceinline__ uint32_t sptr(const void* p) {
    return (uint32_t)__cvta_generic_to_shared(p);
}
__device__ __forceinline__ unsigned fkey(float s) {
    unsigned u = __float_as_uint(s);
    return (u & 0x80000000u) ? ~u : (u | 0x80000000u);
}
__device__ __forceinline__ float unfkey(unsigned k) {
    return (k & 0x80000000u) ? __uint_as_float(k ^ 0x80000000u) : __uint_as_float(~k);
}
__device__ __forceinline__ uint32_t swz64(uint32_t off) {
    return off ^ ((off >> 3) & 0x30);
}
__device__ __forceinline__ void cpa16(uint32_t dst, const void* src) {
    asm volatile("cp.async.cg.shared.global [%0], [%1], 16;" :: "r"(dst), "l"(src));
}
__device__ __forceinline__ void ldsm4(uint32_t& r0, uint32_t& r1, uint32_t& r2,
                                      uint32_t& r3, uint32_t addr) {
    asm volatile("ldmatrix.sync.aligned.m8n8.x4.shared.b16 {%0,%1,%2,%3}, [%4];"
                 : "=r"(r0), "=r"(r1), "=r"(r2), "=r"(r3) : "r"(addr));
}
// fp16-accumulate HMMA: 2x rate vs f32-acc
__device__ __forceinline__ void mma16816h(uint32_t* c, const uint32_t* a,
                                          uint32_t b0, uint32_t b1) {
    asm volatile(
        "mma.sync.aligned.m16n8k16.row.col.f16.f16.f16.f16 "
        "{%0,%1}, {%2,%3,%4,%5}, {%6,%7}, {%0,%1};"
        : "+r"(c[0]), "+r"(c[1])
        : "r"(a[0]), "r"(a[1]), "r"(a[2]), "r"(a[3]), "r"(b0), "r"(b1));
}
__device__ __forceinline__ float warp_dot(const float4* kr, const float4* er, int lane) {
    float d0 = 0.f, d1 = 0.f;
    #pragma unroll
    for (int i = 0; i < 4; i += 2) {
        float4 a0 = kr[lane + i * 32],       b0 = er[lane + i * 32];
        float4 a1 = kr[lane + (i + 1) * 32], b1 = er[lane + (i + 1) * 32];
        d0 = fmaf(a0.x, b0.x, d0); d0 = fmaf(a0.y, b0.y, d0);
        d0 = fmaf(a0.z, b0.z, d0); d0 = fmaf(a0.w, b0.w, d0);
        d1 = fmaf(a1.x, b1.x, d1); d1 = fmaf(a1.y, b1.y, d1);
        d1 = fmaf(a1.z, b1.z, d1); d1 = fmaf(a1.w, b1.w, d1);
    }
    float d = d0 + d1;
    #pragma unroll
    for (int o = 16; o; o >>= 1) d += __shfl_xor_sync(0xffffffffu, d, o);
    return d;
}

// ---------------- K1: fused prep (R8-proven proj, fp16 out) ----------------------
__global__ __launch_bounds__(256) void k_prep(const float* __restrict__ A,
                                              const float* __restrict__ W,
                                              const float* __restrict__ bias,
                                              const float* __restrict__ emb) {
    __shared__ __align__(16) float As[2][64][36];   // [m][k]
    __shared__ __align__(16) float Ws[2][32][68];   // [k][n]
    int tid = threadIdx.x;

    if (blockIdx.x < PROJ_BLKS) {
        if (blockIdx.x == 0) { g_hikey[tid] = 0u; g_hikey[tid + 256] = 0u; }
        int m0 = (blockIdx.x >> 3) * 64;
        int n0 = (blockIdx.x & 7) * 64;
        int tx = tid & 15, ty = tid >> 4;

        {   // prologue: stage 0
            #pragma unroll
            for (int i = 0; i < 2; ++i) {
                int c = tid + i * 256;
                int m = c >> 3, kq = (c & 7) * 4;
                cpa16(sptr(&As[0][m][kq]), &A[(size_t)(m0 + m) * K_D + kq]);
            }
            #pragma unroll
            for (int i = 0; i < 2; ++i) {
                int c = tid + i * 256;
                int kk = c >> 4, nq = (c & 15) * 4;
                cpa16(sptr(&Ws[0][kk][nq]), &W[(size_t)kk * T_DIM + n0 + nq]);
            }
            asm volatile("cp.async.commit_group;" ::: "memory");
        }

        float acc[4][4] = {};
        const int NPT = K_D / 32;                  // 24
        for (int kt = 0; kt < NPT; ++kt) {
            int s = kt & 1;
            if (kt + 1 < NPT) {
                int k0 = (kt + 1) * 32, ns = s ^ 1;
                #pragma unroll
                for (int i = 0; i < 2; ++i) {
                    int c = tid + i * 256;
                    int m = c >> 3, kq = (c & 7) * 4;
                    cpa16(sptr(&As[ns][m][kq]), &A[(size_t)(m0 + m) * K_D + k0 + kq]);
                }
                #pragma unroll
                for (int i = 0; i < 2; ++i) {
                    int c = tid + i * 256;
                    int kk = c >> 4, nq = (c & 15) * 4;
                    cpa16(sptr(&Ws[ns][kk][nq]), &W[(size_t)(k0 + kk) * T_DIM + n0 + nq]);
                }
                asm volatile("cp.async.commit_group;" ::: "memory");
                asm volatile("cp.async.wait_group 1;" ::: "memory");
            } else {
                asm volatile("cp.async.wait_group 0;" ::: "memory");
            }
            __syncthreads();
            #pragma unroll
            for (int kg = 0; kg < 8; ++kg) {
                float4 av[4], bv[4];
                #pragma unroll
                for (int i = 0; i < 4; ++i)
                    av[i] = *(const float4*)&As[s][ty * 4 + i][kg * 4];
                #pragma unroll
                for (int k = 0; k < 4; ++k)
                    bv[k] = *(const float4*)&Ws[s][kg * 4 + k][tx * 4];
                #pragma unroll
                for (int i = 0; i < 4; ++i) {
                    acc[i][0] = fmaf(av[i].x, bv[0].x, acc[i][0]);
                    acc[i][1] = fmaf(av[i].x, bv[0].y, acc[i][1]);
                    acc[i][2] = fmaf(av[i].x, bv[0].z, acc[i][2]);
                    acc[i][3] = fmaf(av[i].x, bv[0].w, acc[i][3]);
                    acc[i][0] = fmaf(av[i].y, bv[1].x, acc[i][0]);
                    acc[i][1] = fmaf(av[i].y, bv[1].y, acc[i][1]);
                    acc[i][2] = fmaf(av[i].y, bv[1].z, acc[i][2]);
                    acc[i][3] = fmaf(av[i].y, bv[1].w, acc[i][3]);
                    acc[i][0] = fmaf(av[i].z, bv[2].x, acc[i][0]);
                    acc[i][1] = fmaf(av[i].z, bv[2].y, acc[i][1]);
                    acc[i][2] = fmaf(av[i].z, bv[2].z, acc[i][2]);
                    acc[i][3] = fmaf(av[i].z, bv[2].w, acc[i][3]);
                    acc[i][0] = fmaf(av[i].w, bv[3].x, acc[i][0]);
                    acc[i][1] = fmaf(av[i].w, bv[3].y, acc[i][1]);
                    acc[i][2] = fmaf(av[i].w, bv[3].z, acc[i][2]);
                    acc[i][3] = fmaf(av[i].w, bv[3].w, acc[i][3]);
                }
            }
            __syncthreads();
        }
        float4 bb = *(const float4*)&bias[n0 + tx * 4];
        #pragma unroll
        for (int i = 0; i < 4; ++i) {
            int m = m0 + ty * 4 + i;
            int n = n0 + tx * 4;
            float x[4] = {acc[i][0] + bb.x, acc[i][1] + bb.y,
                          acc[i][2] + bb.z, acc[i][3] + bb.w};
            *(float4*)&g_kw[(size_t)m * T_DIM + n] = *(float4*)x;
            __half hi[4] = {__float2half_rn(x[0]), __float2half_rn(x[1]),
                            __float2half_rn(x[2]), __float2half_rn(x[3])};
            *(uint2*)&g_A16[(size_t)m * T_DIM + n] = *(uint2*)hi;
        }
    } else {
        int v = (blockIdx.x - PROJ_BLKS) * 8 + (tid >> 5);
        int lane = tid & 31;
        const float4* p = (const float4*)(emb + (size_t)v * T_DIM);
        float4 vals[4];
        float ss = 0.f;
        #pragma unroll
        for (int i = 0; i < 4; ++i) {
            vals[i] = p[lane + i * 32];
            ss += vals[i].x * vals[i].x + vals[i].y * vals[i].y
                + vals[i].z * vals[i].z + vals[i].w * vals[i].w;
        }
        #pragma unroll
        for (int o = 16; o; o >>= 1) ss += __shfl_xor_sync(0xffffffffu, ss, o);
        float inv = 1.0f / fmaxf(sqrtf(ss), EPSF);
        if (lane == 0) g_invn[v] = inv;
        #pragma unroll
        for (int i = 0; i < 4; ++i) {
            __half hi[4];
            hi[0] = __float2half_rn(vals[i].x * inv);
            hi[1] = __float2half_rn(vals[i].y * inv);
            hi[2] = __float2half_rn(vals[i].z * inv);
            hi[3] = __float2half_rn(vals[i].w * inv);
            int idx = (lane + i * 32) * 4;
            *(uint2*)&g_B16[(size_t)v * T_DIM + idx] = *(uint2*)hi;
        }
    }
}

// ---------------- K2: pass1 — fp16-acc HMMA, fp16 scores + tile maxima -----------
__device__ __forceinline__ void fill_stage(uint32_t stg, int m0, int n0, int kt, int tid) {
    int kk = kt * 32;
    #pragma unroll
    for (int i = 0; i < 4; ++i) {
        int c = tid + i * 128;
        int r = c >> 2, cc = c & 3;
        cpa16(stg + swz64(r * 64 + cc * 16),
              &g_A16[(size_t)(m0 + r) * T_DIM + kk + cc * 8]);
    }
    #pragma unroll
    for (int i = 0; i < 4; ++i) {
        int c = tid + i * 128;
        int r = c >> 2, cc = c & 3;
        cpa16(stg + A_STG + swz64(r * 64 + cc * 16),
              &g_B16[(size_t)(n0 + r) * T_DIM + kk + cc * 8]);
    }
    asm volatile("cp.async.commit_group;" ::: "memory");
}

__global__ __launch_bounds__(128, 3) void k_pass1() {
    extern __shared__ __align__(16) char smraw[];
    uint32_t sm0 = (sptr(smraw) + 1023) & ~1023u;
    int tid = threadIdx.x;
    int lane = tid & 31, wid = tid >> 5;
    int warp_m = wid & 1, warp_n = wid >> 1;
    int m0 = blockIdx.x * BM;
    int n0 = blockIdx.y * BN;

    uint32_t acc[4][8][2];                        // half2 pairs: [mb][nb][rowhalf]
    #pragma unroll
    for (int i = 0; i < 4; ++i)
        #pragma unroll
        for (int j = 0; j < 8; ++j) { acc[i][j][0] = 0u; acc[i][j][1] = 0u; }

    #pragma unroll
    for (int p = 0; p < NSTAGE - 1; ++p)
        fill_stage(sm0 + p * STG_BYTES, m0, n0, p, tid);

    int aRow = warp_m * 64 + (lane & 15);
    int aHi  = ((lane >> 4) & 1) * 16;
    int bRow = warp_n * 64 + ((lane >> 4) & 1) * 8 + (lane & 7);
    int bHi  = ((lane >> 3) & 1) * 16;

    for (int kt = 0; kt < NKT; ++kt) {
        asm volatile("cp.async.wait_group 2;" ::: "memory");
        __syncthreads();                          // RAW(stage kt) + WAR(fill below)
        int fk = kt + NSTAGE - 1;
        if (fk < NKT) {
            fill_stage(sm0 + (fk & 3) * STG_BYTES, m0, n0, fk, tid);
        } else {
            asm volatile("cp.async.commit_group;" ::: "memory");  // keep count exact
        }

        uint32_t Ab = sm0 + (kt & 3) * STG_BYTES;
        uint32_t Bb = Ab + A_STG;
        #pragma unroll
        for (int half = 0; half < 2; ++half) {
            uint32_t a[4][4], b[4][4];
            #pragma unroll
            for (int mb = 0; mb < 4; ++mb)
                ldsm4(a[mb][0], a[mb][1], a[mb][2], a[mb][3],
                      Ab + swz64((aRow + mb * 16) * 64 + half * 32 + aHi));
            #pragma unroll
            for (int nbb = 0; nbb < 4; ++nbb)
                ldsm4(b[nbb][0], b[nbb][1], b[nbb][2], b[nbb][3],
                      Bb + swz64((bRow + nbb * 16) * 64 + half * 32 + bHi));
            #pragma unroll
            for (int mb = 0; mb < 4; ++mb)
                #pragma unroll
                for (int nbb = 0; nbb < 4; ++nbb) {
                    mma16816h(acc[mb][2 * nbb],     a[mb], b[nbb][0], b[nbb][1]);
                    mma16816h(acc[mb][2 * nbb + 1], a[mb], b[nbb][2], b[nbb][3]);
                }
        }
    }
    asm volatile("cp.async.wait_group 0;" ::: "memory");
    __syncthreads();                              // smem reused by epilogue

    // epilogue: raw half2 score store + per-(row, tile) max + global hi-max
    float* red = (float*)smraw;                   // [128][2]
    #pragma unroll
    for (int mb = 0; mb < 4; ++mb) {
        #pragma unroll
        for (int rh = 0; rh < 2; ++rh) {          // reg 0: row, reg 1: row+8
            int row_l = warp_m * 64 + mb * 16 + rh * 8 + (lane >> 2);
            int row = m0 + row_l;
            float bs = -3.0e38f;
            #pragma unroll
            for (int nb = 0; nb < 8; ++nb) {
                uint32_t h2 = acc[mb][nb][rh];
                *(uint32_t*)&g_s16[(size_t)row * V_SZ + n0 + warp_n * 64 +
                                   nb * 8 + (lane & 3) * 2] = h2;
                __half2 hh = *reinterpret_cast<__half2*>(&h2);
                bs = fmaxf(bs, fmaxf(__half2float(__low2half(hh)),
                                     __half2float(__high2half(hh))));
            }
            #pragma unroll
            for (int o = 1; o <= 2; o <<= 1)
                bs = fmaxf(bs, __shfl_xor_sync(0xffffffffu, bs, o));
            if ((lane & 3) == 0) red[row_l * 2 + warp_n] = bs;
        }
    }
    __syncthreads();
    if (tid < 128) {
        float tm = fmaxf(red[tid * 2], red[tid * 2 + 1]);
        g_tilemax[(size_t)(m0 + tid) * NTILE + blockIdx.y] = tm;
        atomicMax(&g_hikey[m0 + tid], fkey(tm));
    }
}

// ---------------- K3: pass2 — prune -> exact rescore -> gather ------------------
__global__ __launch_bounds__(128) void k_pass2(const float* __restrict__ emb,
                                               float* __restrict__ out) {
    int m = blockIdx.x;
    int tid = threadIdx.x, wid = tid >> 5, lane = tid & 31;
    __shared__ int s_tcnt, s_ccnt;
    __shared__ float s_thr;
    __shared__ float s_red[4];
    __shared__ short s_tiles[NTILE];
    __shared__ int s_cand[256];
    const float4* kr = (const float4*)(g_kw + (size_t)m * T_DIM);

    {   // ||kw_m||^2, threshold, init
        float4 a = kr[tid];
        float ss = a.x * a.x + a.y * a.y + a.z * a.z + a.w * a.w;
        #pragma unroll
        for (int o = 16; o; o >>= 1) ss += __shfl_xor_sync(0xffffffffu, ss, o);
        if (lane == 0) s_red[wid] = ss;
        if (tid == 0) { s_tcnt = 0; s_ccnt = 0; g_best[m] = 0ull; }
    }
    __syncthreads();
    if (tid == 0) {
        float nrm = sqrtf(s_red[0] + s_red[1] + s_red[2] + s_red[3]);
        s_thr = unfkey(g_hikey[m]) - 0.025f * nrm;   // fp16-accum margin
    }
    __syncthreads();
    float thr = s_thr;

    for (int t = tid; t < NTILE; t += 128)
        if (g_tilemax[(size_t)m * NTILE + t] >= thr) {
            int s = atomicAdd(&s_tcnt, 1);
            s_tiles[s] = (short)t;
        }
    __syncthreads();

    int ntl = s_tcnt;
    for (int i = 0; i < ntl; ++i) {
        int v = (int)s_tiles[i] * 128 + tid;
        float sv = __half2float(g_s16[(size_t)m * V_SZ + v]);
        if (sv >= thr) {
            int s = atomicAdd(&s_ccnt, 1);
            if (s < 256) s_cand[s] = v;
            else {                                 // overflow fallback (rare)
                const float4* er = (const float4*)(emb + (size_t)v * T_DIM);
                float d = 0.f;
                for (int q = 0; q < 128; ++q) {
                    float4 a = kr[q], bb = er[q];
                    d = fmaf(a.x, bb.x, d); d = fmaf(a.y, bb.y, d);
                    d = fmaf(a.z, bb.z, d); d = fmaf(a.w, bb.w, d);
                }
                float ex = d * g_invn[v];
                unsigned long long pk = ((unsigned long long)fkey(ex) << 32) |
                                        (0xFFFFFFFFu - (unsigned)v);
                atomicMax(&g_best[m], pk);
            }
        }
    }
    __syncthreads();

    int nc = min(s_ccnt, 256);
    for (int c = wid; c < nc; c += 4) {
        int v = s_cand[c];
        const float4* er = (const float4*)(emb + (size_t)v * T_DIM);
        float d = warp_dot(kr, er, lane);
        if (lane == 0) {
            float ex = d * g_invn[v];
            unsigned long long pk = ((unsigned long long)fkey(ex) << 32) |
                                    (0xFFFFFFFFu - (unsigned)v);
            atomicMax(&g_best[m], pk);
        }
    }
    __syncthreads();

    unsigned v = 0xFFFFFFFFu - (unsigned)(g_best[m] & 0xFFFFFFFFull);
    ((float4*)(out + (size_t)m * T_DIM))[tid] =
        ((const float4*)(emb + (size_t)v * T_DIM))[tid];
}

// ---------------- launcher --------------------------------------------------------
extern "C" void kernel_launch(void* const* d_in, const int* in_sizes, int n_in,
                              void* d_out, int out_size) {
    const float* audio = (const float*)d_in[0];
    const float* W     = (const float*)d_in[1];
    const float* b     = (const float*)d_in[2];
    const float* emb   = (const float*)d_in[3];
    float* out         = (float*)d_out;

    cudaFuncSetAttribute(k_pass1, cudaFuncAttributeMaxDynamicSharedMemorySize, DSMEM);

    k_prep<<<PROJ_BLKS + V_SZ / 8, 256>>>(audio, W, b, emb);
    dim3 g3(M_KW / BM, V_SZ / BN);       // (4, 386): x fastest -> B-tile L2 reuse
    k_pass1<<<g3, 128, DSMEM>>>();
    k_pass2<<<M_KW, 128>>>(emb, out);
}

// round 12
// speedup vs baseline: 1.0113x; 1.0113x over previous
#include <cuda_runtime.h>
#include <cuda_bf16.h>
#include <cstdint>

#define M_KW 512
#define K_D  768
#define T_DIM 512
#define V_SZ 49408
#define NTILE (V_SZ / 128)         // 386
#define EPSF 1e-8f

// pass-1 GEMM tiling (R8 proven: pass1 ~79us)
#define BM 128
#define BN 128
#define BK 32
#define NKT (T_DIM / BK)           // 16
#define NSTAGE 4
#define A_STG (BM * 64)
#define B_STG (BN * 64)
#define STG_BYTES (A_STG + B_STG)  // 16384
#define DSMEM (NSTAGE * STG_BYTES + 1024)

#define PROJ_BLKS 64               // 64x64 proj tiles

// ---------------- device scratch ------------------------------------------------
__device__ float g_kw[M_KW * T_DIM];                       // fp32 projected keywords
__device__ __nv_bfloat16 g_A16[M_KW * T_DIM];              // bf16 of g_kw
__device__ __nv_bfloat16 g_B16[(size_t)V_SZ * T_DIM];      // bf16 normalized emb
__device__ float g_invn[V_SZ];                             // 1/max(||emb_v||,eps)
__device__ __nv_bfloat16 g_s16[(size_t)M_KW * V_SZ];       // bf16 scores (50 MB)
__device__ float g_tilemax[(size_t)M_KW * NTILE];          // per-row per-tile max
__device__ unsigned g_hikey[M_KW];                         // fkey(max bf16 score)
__device__ unsigned long long g_best[M_KW];                // packed exact argmax

// ---------------- helpers -------------------------------------------------------
__device__ __forceinline__ uint32_t sptr(const void* p) {
    return (uint32_t)__cvta_generic_to_shared(p);
}
__device__ __forceinline__ unsigned fkey(float s) {
    unsigned u = __float_as_uint(s);
    return (u & 0x80000000u) ? ~u : (u | 0x80000000u);
}
__device__ __forceinline__ float unfkey(unsigned k) {
    return (k & 0x80000000u) ? __uint_as_float(k ^ 0x80000000u) : __uint_as_float(~k);
}
__device__ __forceinline__ uint32_t swz64(uint32_t off) {
    return off ^ ((off >> 3) & 0x30);
}
__device__ __forceinline__ void cpa16(uint32_t dst, const void* src) {
    asm volatile("cp.async.cg.shared.global [%0], [%1], 16;" :: "r"(dst), "l"(src));
}
__device__ __forceinline__ void ldsm4(uint32_t& r0, uint32_t& r1, uint32_t& r2,
                                      uint32_t& r3, uint32_t addr) {
    asm volatile("ldmatrix.sync.aligned.m8n8.x4.shared.b16 {%0,%1,%2,%3}, [%4];"
                 : "=r"(r0), "=r"(r1), "=r"(r2), "=r"(r3) : "r"(addr));
}
__device__ __forceinline__ void mma16816(float* c, const uint32_t* a,
                                         uint32_t b0, uint32_t b1) {
    asm volatile(
        "mma.sync.aligned.m16n8k16.row.col.f32.bf16.bf16.f32 "
        "{%0,%1,%2,%3}, {%4,%5,%6,%7}, {%8,%9}, {%0,%1,%2,%3};"
        : "+f"(c[0]), "+f"(c[1]), "+f"(c[2]), "+f"(c[3])
        : "r"(a[0]), "r"(a[1]), "r"(a[2]), "r"(a[3]), "r"(b0), "r"(b1));
}
__device__ __forceinline__ float warp_dot(const float4* kr, const float4* er, int lane) {
    float d0 = 0.f, d1 = 0.f;
    #pragma unroll
    for (int i = 0; i < 4; i += 2) {
        float4 a0 = kr[lane + i * 32],       b0 = er[lane + i * 32];
        float4 a1 = kr[lane + (i + 1) * 32], b1 = er[lane + (i + 1) * 32];
        d0 = fmaf(a0.x, b0.x, d0); d0 = fmaf(a0.y, b0.y, d0);
        d0 = fmaf(a0.z, b0.z, d0); d0 = fmaf(a0.w, b0.w, d0);
        d1 = fmaf(a1.x, b1.x, d1); d1 = fmaf(a1.y, b1.y, d1);
        d1 = fmaf(a1.z, b1.z, d1); d1 = fmaf(a1.w, b1.w, d1);
    }
    float d = d0 + d1;
    #pragma unroll
    for (int o = 16; o; o >>= 1) d += __shfl_xor_sync(0xffffffffu, d, o);
    return d;
}

// ---------------- K1: fused prep — low-smem proj (19KB) for prepB occupancy ------
// blocks [0,64): cp.async BK=16 double-buffered fp32 proj: 64x64 tile
// blocks [64, 64+6176): normalize emb rows -> g_B16 bf16 + g_invn
__global__ __launch_bounds__(256) void k_prep(const float* __restrict__ A,
                                              const float* __restrict__ W,
                                              const float* __restrict__ bias,
                                              const float* __restrict__ emb) {
    __shared__ __align__(16) float As[2][64][20];   // [m][k], 80B rows
    __shared__ __align__(16) float Ws[2][16][68];   // [k][n], 272B rows
    int tid = threadIdx.x;

    if (blockIdx.x < PROJ_BLKS) {
        if (blockIdx.x == 0) { g_hikey[tid] = 0u; g_hikey[tid + 256] = 0u; }
        int m0 = (blockIdx.x >> 3) * 64;
        int n0 = (blockIdx.x & 7) * 64;
        int tx = tid & 15, ty = tid >> 4;
        int am = tid >> 2, aq = (tid & 3) * 4;      // A: 64 rows x 4 chunks
        int wk = tid >> 4, wq = (tid & 15) * 4;     // W: 16 rows x 16 chunks

        // prologue: stage 0
        cpa16(sptr(&As[0][am][aq]), &A[(size_t)(m0 + am) * K_D + aq]);
        cpa16(sptr(&Ws[0][wk][wq]), &W[(size_t)wk * T_DIM + n0 + wq]);
        asm volatile("cp.async.commit_group;" ::: "memory");

        float acc[4][4] = {};
        const int NPT = K_D / 16;                   // 48
        for (int kt = 0; kt < NPT; ++kt) {
            int s = kt & 1;
            if (kt + 1 < NPT) {
                int k0 = (kt + 1) * 16, ns = s ^ 1;
                cpa16(sptr(&As[ns][am][aq]), &A[(size_t)(m0 + am) * K_D + k0 + aq]);
                cpa16(sptr(&Ws[ns][wk][wq]), &W[(size_t)(k0 + wk) * T_DIM + n0 + wq]);
                asm volatile("cp.async.commit_group;" ::: "memory");
                asm volatile("cp.async.wait_group 1;" ::: "memory");
            } else {
                asm volatile("cp.async.wait_group 0;" ::: "memory");
            }
            __syncthreads();
            #pragma unroll
            for (int kg = 0; kg < 4; ++kg) {
                float4 av[4], bv[4];
                #pragma unroll
                for (int i = 0; i < 4; ++i)
                    av[i] = *(const float4*)&As[s][ty * 4 + i][kg * 4];
                #pragma unroll
                for (int k = 0; k < 4; ++k)
                    bv[k] = *(const float4*)&Ws[s][kg * 4 + k][tx * 4];
                #pragma unroll
                for (int i = 0; i < 4; ++i) {
                    acc[i][0] = fmaf(av[i].x, bv[0].x, acc[i][0]);
                    acc[i][1] = fmaf(av[i].x, bv[0].y, acc[i][1]);
                    acc[i][2] = fmaf(av[i].x, bv[0].z, acc[i][2]);
                    acc[i][3] = fmaf(av[i].x, bv[0].w, acc[i][3]);
                    acc[i][0] = fmaf(av[i].y, bv[1].x, acc[i][0]);
                    acc[i][1] = fmaf(av[i].y, bv[1].y, acc[i][1]);
                    acc[i][2] = fmaf(av[i].y, bv[1].z, acc[i][2]);
                    acc[i][3] = fmaf(av[i].y, bv[1].w, acc[i][3]);
                    acc[i][0] = fmaf(av[i].z, bv[2].x, acc[i][0]);
                    acc[i][1] = fmaf(av[i].z, bv[2].y, acc[i][1]);
                    acc[i][2] = fmaf(av[i].z, bv[2].z, acc[i][2]);
                    acc[i][3] = fmaf(av[i].z, bv[2].w, acc[i][3]);
                    acc[i][0] = fmaf(av[i].w, bv[3].x, acc[i][0]);
                    acc[i][1] = fmaf(av[i].w, bv[3].y, acc[i][1]);
                    acc[i][2] = fmaf(av[i].w, bv[3].z, acc[i][2]);
                    acc[i][3] = fmaf(av[i].w, bv[3].w, acc[i][3]);
                }
            }
            __syncthreads();                        // WAR before next prefetch reuse
        }
        float4 bb = *(const float4*)&bias[n0 + tx * 4];
        #pragma unroll
        for (int i = 0; i < 4; ++i) {
            int m = m0 + ty * 4 + i;
            int n = n0 + tx * 4;
            float x[4] = {acc[i][0] + bb.x, acc[i][1] + bb.y,
                          acc[i][2] + bb.z, acc[i][3] + bb.w};
            *(float4*)&g_kw[(size_t)m * T_DIM + n] = *(float4*)x;
            __nv_bfloat16 hi[4] = {__float2bfloat16(x[0]), __float2bfloat16(x[1]),
                                   __float2bfloat16(x[2]), __float2bfloat16(x[3])};
            *(uint2*)&g_A16[(size_t)m * T_DIM + n] = *(uint2*)hi;
        }
    } else {
        int v = (blockIdx.x - PROJ_BLKS) * 8 + (tid >> 5);
        int lane = tid & 31;
        const float4* p = (const float4*)(emb + (size_t)v * T_DIM);
        float4 vals[4];
        float ss = 0.f;
        #pragma unroll
        for (int i = 0; i < 4; ++i) {
            vals[i] = p[lane + i * 32];
            ss += vals[i].x * vals[i].x + vals[i].y * vals[i].y
                + vals[i].z * vals[i].z + vals[i].w * vals[i].w;
        }
        #pragma unroll
        for (int o = 16; o; o >>= 1) ss += __shfl_xor_sync(0xffffffffu, ss, o);
        float inv = 1.0f / fmaxf(sqrtf(ss), EPSF);
        if (lane == 0) g_invn[v] = inv;
        #pragma unroll
        for (int i = 0; i < 4; ++i) {
            __nv_bfloat16 hi[4];
            hi[0] = __float2bfloat16(vals[i].x * inv);
            hi[1] = __float2bfloat16(vals[i].y * inv);
            hi[2] = __float2bfloat16(vals[i].z * inv);
            hi[3] = __float2bfloat16(vals[i].w * inv);
            int idx = (lane + i * 32) * 4;
            *(uint2*)&g_B16[(size_t)v * T_DIM + idx] = *(uint2*)hi;
        }
    }
}

// ---------------- K2: pass1 — exact R8 kernel ------------------------------------
__device__ __forceinline__ void fill_stage(uint32_t stg, int m0, int n0, int kt, int tid) {
    int kk = kt * 32;
    #pragma unroll
    for (int i = 0; i < 4; ++i) {
        int c = tid + i * 128;
        int r = c >> 2, cc = c & 3;
        cpa16(stg + swz64(r * 64 + cc * 16),
              &g_A16[(size_t)(m0 + r) * T_DIM + kk + cc * 8]);
    }
    #pragma unroll
    for (int i = 0; i < 4; ++i) {
        int c = tid + i * 128;
        int r = c >> 2, cc = c & 3;
        cpa16(stg + A_STG + swz64(r * 64 + cc * 16),
              &g_B16[(size_t)(n0 + r) * T_DIM + kk + cc * 8]);
    }
    asm volatile("cp.async.commit_group;" ::: "memory");
}

__global__ __launch_bounds__(128, 2) void k_pass1() {
    extern __shared__ __align__(16) char smraw[];
    uint32_t sm0 = (sptr(smraw) + 1023) & ~1023u;
    int tid = threadIdx.x;
    int lane = tid & 31, wid = tid >> 5;
    int warp_m = wid & 1, warp_n = wid >> 1;
    int m0 = blockIdx.x * BM;
    int n0 = blockIdx.y * BN;

    float acc[4][8][4];
    #pragma unroll
    for (int i = 0; i < 4; ++i)
        #pragma unroll
        for (int j = 0; j < 8; ++j)
            #pragma unroll
            for (int k = 0; k < 4; ++k) acc[i][j][k] = 0.f;

    #pragma unroll
    for (int p = 0; p < NSTAGE - 1; ++p)
        fill_stage(sm0 + p * STG_BYTES, m0, n0, p, tid);

    int aRow = warp_m * 64 + (lane & 15);
    int aHi  = ((lane >> 4) & 1) * 16;
    int bRow = warp_n * 64 + ((lane >> 4) & 1) * 8 + (lane & 7);
    int bHi  = ((lane >> 3) & 1) * 16;

    for (int kt = 0; kt < NKT; ++kt) {
        asm volatile("cp.async.wait_group 2;" ::: "memory");
        __syncthreads();
        int fk = kt + NSTAGE - 1;
        if (fk < NKT) {
            fill_stage(sm0 + (fk & 3) * STG_BYTES, m0, n0, fk, tid);
        } else {
            asm volatile("cp.async.commit_group;" ::: "memory");
        }

        uint32_t Ab = sm0 + (kt & 3) * STG_BYTES;
        uint32_t Bb = Ab + A_STG;
        #pragma unroll
        for (int half = 0; half < 2; ++half) {
            uint32_t a[4][4], b[4][4];
            #pragma unroll
            for (int mb = 0; mb < 4; ++mb)
                ldsm4(a[mb][0], a[mb][1], a[mb][2], a[mb][3],
                      Ab + swz64((aRow + mb * 16) * 64 + half * 32 + aHi));
            #pragma unroll
            for (int nbb = 0; nbb < 4; ++nbb)
                ldsm4(b[nbb][0], b[nbb][1], b[nbb][2], b[nbb][3],
                      Bb + swz64((bRow + nbb * 16) * 64 + half * 32 + bHi));
            #pragma unroll
            for (int mb = 0; mb < 4; ++mb)
                #pragma unroll
                for (int nbb = 0; nbb < 4; ++nbb) {
                    mma16816(acc[mb][2 * nbb],     a[mb], b[nbb][0], b[nbb][1]);
                    mma16816(acc[mb][2 * nbb + 1], a[mb], b[nbb][2], b[nbb][3]);
                }
        }
    }
    asm volatile("cp.async.wait_group 0;" ::: "memory");
    __syncthreads();

    // epilogue: bf16 score store + per-(row, tile) max + global hi-max
    float* red = (float*)smraw;                   // [128][2]
    #pragma unroll
    for (int mb = 0; mb < 4; ++mb) {
        #pragma unroll
        for (int half = 0; half < 2; ++half) {
            int row_l = warp_m * 64 + mb * 16 + half * 8 + (lane >> 2);
            int row = m0 + row_l;
            float bs = -3.0e38f;
            #pragma unroll
            for (int nb = 0; nb < 8; ++nb) {
                float2 s = make_float2(acc[mb][nb][half * 2],
                                       acc[mb][nb][half * 2 + 1]);
                __nv_bfloat162 h = __float22bfloat162_rn(s);
                *(__nv_bfloat162*)&g_s16[(size_t)row * V_SZ + n0 + warp_n * 64 +
                                         nb * 8 + (lane & 3) * 2] = h;
                bs = fmaxf(bs, fmaxf(__bfloat162float(h.x), __bfloat162float(h.y)));
            }
            #pragma unroll
            for (int o = 1; o <= 2; o <<= 1)
                bs = fmaxf(bs, __shfl_xor_sync(0xffffffffu, bs, o));
            if ((lane & 3) == 0) red[row_l * 2 + warp_n] = bs;
        }
    }
    __syncthreads();
    if (tid < 128) {
        float tm = fmaxf(red[tid * 2], red[tid * 2 + 1]);
        g_tilemax[(size_t)(m0 + tid) * NTILE + blockIdx.y] = tm;
        atomicMax(&g_hikey[m0 + tid], fkey(tm));
    }
}

// ---------------- K3: pass2 — prune -> exact rescore -> gather ------------------
__global__ __launch_bounds__(128) void k_pass2(const float* __restrict__ emb,
                                               float* __restrict__ out) {
    int m = blockIdx.x;
    int tid = threadIdx.x, wid = tid >> 5, lane = tid & 31;
    __shared__ int s_tcnt, s_ccnt;
    __shared__ float s_thr;
    __shared__ float s_red[4];
    __shared__ short s_tiles[NTILE];
    __shared__ int s_cand[256];
    const float4* kr = (const float4*)(g_kw + (size_t)m * T_DIM);

    {   // ||kw_m||^2, threshold, init
        float4 a = kr[tid];
        float ss = a.x * a.x + a.y * a.y + a.z * a.z + a.w * a.w;
        #pragma unroll
        for (int o = 16; o; o >>= 1) ss += __shfl_xor_sync(0xffffffffu, ss, o);
        if (lane == 0) s_red[wid] = ss;
        if (tid == 0) { s_tcnt = 0; s_ccnt = 0; g_best[m] = 0ull; }
    }
    __syncthreads();
    if (tid == 0) {
        float nrm = sqrtf(s_red[0] + s_red[1] + s_red[2] + s_red[3]);
        s_thr = unfkey(g_hikey[m]) - 0.013f * nrm;
    }
    __syncthreads();
    float thr = s_thr;

    for (int t = tid; t < NTILE; t += 128)
        if (g_tilemax[(size_t)m * NTILE + t] >= thr) {
            int s = atomicAdd(&s_tcnt, 1);
            s_tiles[s] = (short)t;
        }
    __syncthreads();

    int ntl = s_tcnt;
    for (int i = 0; i < ntl; ++i) {
        int v = (int)s_tiles[i] * 128 + tid;
        float sv = __bfloat162float(g_s16[(size_t)m * V_SZ + v]);
        if (sv >= thr) {
            int s = atomicAdd(&s_ccnt, 1);
            if (s < 256) s_cand[s] = v;
            else {                                 // overflow fallback (rare)
                const float4* er = (const float4*)(emb + (size_t)v * T_DIM);
                float d = 0.f;
                for (int q = 0; q < 128; ++q) {
                    float4 a = kr[q], bb = er[q];
                    d = fmaf(a.x, bb.x, d); d = fmaf(a.y, bb.y, d);
                    d = fmaf(a.z, bb.z, d); d = fmaf(a.w, bb.w, d);
                }
                float ex = d * g_invn[v];
                unsigned long long pk = ((unsigned long long)fkey(ex) << 32) |
                                        (0xFFFFFFFFu - (unsigned)v);
                atomicMax(&g_best[m], pk);
            }
        }
    }
    __syncthreads();

    int nc = min(s_ccnt, 256);
    for (int c = wid; c < nc; c += 4) {
        int v = s_cand[c];
        const float4* er = (const float4*)(emb + (size_t)v * T_DIM);
        float d = warp_dot(kr, er, lane);
        if (lane == 0) {
            float ex = d * g_invn[v];
            unsigned long long pk = ((unsigned long long)fkey(ex) << 32) |
                                    (0xFFFFFFFFu - (unsigned)v);
            atomicMax(&g_best[m], pk);
        }
    }
    __syncthreads();

    unsigned v = 0xFFFFFFFFu - (unsigned)(g_best[m] & 0xFFFFFFFFull);
    ((float4*)(out + (size_t)m * T_DIM))[tid] =
        ((const float4*)(emb + (size_t)v * T_DIM))[tid];
}

// ---------------- launcher --------------------------------------------------------
extern "C" void kernel_launch(void* const* d_in, const int* in_sizes, int n_in,
                              void* d_out, int out_size) {
    const float* audio = (const float*)d_in[0];
    const float* W     = (const float*)d_in[1];
    const float* b     = (const float*)d_in[2];
    const float* emb   = (const float*)d_in[3];
    float* out         = (float*)d_out;

    cudaFuncSetAttribute(k_pass1, cudaFuncAttributeMaxDynamicSharedMemorySize, DSMEM);

    k_prep<<<PROJ_BLKS + V_SZ / 8, 256>>>(audio, W, b, emb);
    dim3 g3(M_KW / BM, V_SZ / BN);       // (4, 386)
    k_pass1<<<g3, 128, DSMEM>>>();
    k_pass2<<<M_KW, 128>>>(emb, out);
}

// round 13
// speedup vs baseline: 1.0715x; 1.0595x over previous
#include <cuda_runtime.h>
#include <cuda_bf16.h>
#include <cstdint>

#define M_KW 512
#define K_D  768
#define T_DIM 512
#define V_SZ 49408
#define NTILE (V_SZ / 128)         // 386
#define EPSF 1e-8f

// pass-1 GEMM tiling
#define BM 128
#define BN 128
#define BK 32
#define NKT (T_DIM / BK)           // 16
#define NSTAGE 4
#define A_STG (BM * 64)
#define B_STG (BN * 64)
#define STG_BYTES (A_STG + B_STG)  // 16384
#define DSMEM (NSTAGE * STG_BYTES + 1024)

#define PROJ_BLKS 128              // 64x32 proj tiles: (m 8) x (n 16)

// ---------------- device scratch ------------------------------------------------
__device__ float g_kw[M_KW * T_DIM];                       // fp32 projected keywords
__device__ __nv_bfloat16 g_A16[M_KW * T_DIM];              // bf16 of g_kw
__device__ __nv_bfloat16 g_B16[(size_t)V_SZ * T_DIM];      // bf16 normalized emb
__device__ float g_invn[V_SZ];                             // 1/max(||emb_v||,eps)
__device__ __nv_bfloat16 g_s16[(size_t)M_KW * V_SZ];       // bf16 scores (50 MB)
__device__ float g_tilemax[(size_t)M_KW * NTILE];          // per-row per-tile max
__device__ unsigned g_hikey[M_KW];                         // fkey(max bf16 score)
__device__ unsigned long long g_best[M_KW];                // packed exact argmax

// ---------------- helpers -------------------------------------------------------
__device__ __forceinline__ uint32_t sptr(const void* p) {
    return (uint32_t)__cvta_generic_to_shared(p);
}
__device__ __forceinline__ unsigned fkey(float s) {
    unsigned u = __float_as_uint(s);
    return (u & 0x80000000u) ? ~u : (u | 0x80000000u);
}
__device__ __forceinline__ float unfkey(unsigned k) {
    return (k & 0x80000000u) ? __uint_as_float(k ^ 0x80000000u) : __uint_as_float(~k);
}
__device__ __forceinline__ uint32_t swz64(uint32_t off) {
    return off ^ ((off >> 3) & 0x30);
}
__device__ __forceinline__ void cpa16(uint32_t dst, const void* src) {
    asm volatile("cp.async.cg.shared.global [%0], [%1], 16;" :: "r"(dst), "l"(src));
}
__device__ __forceinline__ void ldsm4(uint32_t& r0, uint32_t& r1, uint32_t& r2,
                                      uint32_t& r3, uint32_t addr) {
    asm volatile("ldmatrix.sync.aligned.m8n8.x4.shared.b16 {%0,%1,%2,%3}, [%4];"
                 : "=r"(r0), "=r"(r1), "=r"(r2), "=r"(r3) : "r"(addr));
}
__device__ __forceinline__ void mma16816(float* c, const uint32_t* a,
                                         uint32_t b0, uint32_t b1) {
    asm volatile(
        "mma.sync.aligned.m16n8k16.row.col.f32.bf16.bf16.f32 "
        "{%0,%1,%2,%3}, {%4,%5,%6,%7}, {%8,%9}, {%0,%1,%2,%3};"
        : "+f"(c[0]), "+f"(c[1]), "+f"(c[2]), "+f"(c[3])
        : "r"(a[0]), "r"(a[1]), "r"(a[2]), "r"(a[3]), "r"(b0), "r"(b1));
}
__device__ __forceinline__ float warp_dot(const float4* kr, const float4* er, int lane) {
    float d0 = 0.f, d1 = 0.f;
    #pragma unroll
    for (int i = 0; i < 4; i += 2) {
        float4 a0 = kr[lane + i * 32],       b0 = er[lane + i * 32];
        float4 a1 = kr[lane + (i + 1) * 32], b1 = er[lane + (i + 1) * 32];
        d0 = fmaf(a0.x, b0.x, d0); d0 = fmaf(a0.y, b0.y, d0);
        d0 = fmaf(a0.z, b0.z, d0); d0 = fmaf(a0.w, b0.w, d0);
        d1 = fmaf(a1.x, b1.x, d1); d1 = fmaf(a1.y, b1.y, d1);
        d1 = fmaf(a1.z, b1.z, d1); d1 = fmaf(a1.w, b1.w, d1);
    }
    float d = d0 + d1;
    #pragma unroll
    for (int o = 16; o; o >>= 1) d += __shfl_xor_sync(0xffffffffu, d, o);
    return d;
}

// ---------------- K1: fused prep — 128 proj blocks, BK=32, 27KB smem -------------
// blocks [0,128): cp.async double-buffered fp32 proj: 64x32 tile of kw
// blocks [128, 128+6176): normalize emb rows -> g_B16 bf16 + g_invn (8 blk/SM)
__global__ __launch_bounds__(256) void k_prep(const float* __restrict__ A,
                                              const float* __restrict__ W,
                                              const float* __restrict__ bias,
                                              const float* __restrict__ emb) {
    __shared__ __align__(16) float As[2][64][36];   // [m][k], 144B rows -> 18KB
    __shared__ __align__(16) float Ws[2][32][36];   // [k][n], 144B rows -> 9KB
    int tid = threadIdx.x;

    if (blockIdx.x < PROJ_BLKS) {
        if (blockIdx.x == 0) { g_hikey[tid] = 0u; g_hikey[tid + 256] = 0u; }
        int m0 = (blockIdx.x >> 4) * 64;           // 8 m-tiles
        int n0 = (blockIdx.x & 15) * 32;           // 16 n-tiles
        int tx = tid & 15, ty = tid >> 4;          // 16 n-pos x 16 m-pos

        // prologue: stage 0  (A: 512 chunks of 16B; W: 256 chunks)
        {
            #pragma unroll
            for (int i = 0; i < 2; ++i) {
                int c = tid + i * 256;
                int m = c >> 3, kq = (c & 7) * 4;
                cpa16(sptr(&As[0][m][kq]), &A[(size_t)(m0 + m) * K_D + kq]);
            }
            {
                int kk = tid >> 3, nq = (tid & 7) * 4;
                cpa16(sptr(&Ws[0][kk][nq]), &W[(size_t)kk * T_DIM + n0 + nq]);
            }
            asm volatile("cp.async.commit_group;" ::: "memory");
        }

        float acc[4][2] = {};
        const int NPT = K_D / 32;                  // 24
        for (int kt = 0; kt < NPT; ++kt) {
            int s = kt & 1;
            if (kt + 1 < NPT) {
                int k0 = (kt + 1) * 32, ns = s ^ 1;
                #pragma unroll
                for (int i = 0; i < 2; ++i) {
                    int c = tid + i * 256;
                    int m = c >> 3, kq = (c & 7) * 4;
                    cpa16(sptr(&As[ns][m][kq]), &A[(size_t)(m0 + m) * K_D + k0 + kq]);
                }
                {
                    int kk = tid >> 3, nq = (tid & 7) * 4;
                    cpa16(sptr(&Ws[ns][kk][nq]), &W[(size_t)(k0 + kk) * T_DIM + n0 + nq]);
                }
                asm volatile("cp.async.commit_group;" ::: "memory");
                asm volatile("cp.async.wait_group 1;" ::: "memory");
            } else {
                asm volatile("cp.async.wait_group 0;" ::: "memory");
            }
            __syncthreads();
            #pragma unroll
            for (int kg = 0; kg < 8; ++kg) {       // groups of 4 k
                float4 av[4];
                float2 bv[4];
                #pragma unroll
                for (int i = 0; i < 4; ++i)
                    av[i] = *(const float4*)&As[s][ty * 4 + i][kg * 4];
                #pragma unroll
                for (int k = 0; k < 4; ++k)
                    bv[k] = *(const float2*)&Ws[s][kg * 4 + k][tx * 2];
                #pragma unroll
                for (int i = 0; i < 4; ++i) {
                    acc[i][0] = fmaf(av[i].x, bv[0].x, acc[i][0]);
                    acc[i][1] = fmaf(av[i].x, bv[0].y, acc[i][1]);
                    acc[i][0] = fmaf(av[i].y, bv[1].x, acc[i][0]);
                    acc[i][1] = fmaf(av[i].y, bv[1].y, acc[i][1]);
                    acc[i][0] = fmaf(av[i].z, bv[2].x, acc[i][0]);
                    acc[i][1] = fmaf(av[i].z, bv[2].y, acc[i][1]);
                    acc[i][0] = fmaf(av[i].w, bv[3].x, acc[i][0]);
                    acc[i][1] = fmaf(av[i].w, bv[3].y, acc[i][1]);
                }
            }
            __syncthreads();                       // WAR before next prefetch reuse
        }
        float bb0 = bias[n0 + tx * 2], bb1 = bias[n0 + tx * 2 + 1];
        #pragma unroll
        for (int i = 0; i < 4; ++i) {
            int m = m0 + ty * 4 + i;
            int n = n0 + tx * 2;
            float x0 = acc[i][0] + bb0, x1 = acc[i][1] + bb1;
            *(float2*)&g_kw[(size_t)m * T_DIM + n] = make_float2(x0, x1);
            __nv_bfloat162 h = __float22bfloat162_rn(make_float2(x0, x1));
            *(__nv_bfloat162*)&g_A16[(size_t)m * T_DIM + n] = h;
        }
    } else {
        int v = (blockIdx.x - PROJ_BLKS) * 8 + (tid >> 5);
        int lane = tid & 31;
        const float4* p = (const float4*)(emb + (size_t)v * T_DIM);
        float4 vals[4];
        float ss = 0.f;
        #pragma unroll
        for (int i = 0; i < 4; ++i) {
            vals[i] = p[lane + i * 32];
            ss += vals[i].x * vals[i].x + vals[i].y * vals[i].y
                + vals[i].z * vals[i].z + vals[i].w * vals[i].w;
        }
        #pragma unroll
        for (int o = 16; o; o >>= 1) ss += __shfl_xor_sync(0xffffffffu, ss, o);
        float inv = 1.0f / fmaxf(sqrtf(ss), EPSF);
        if (lane == 0) g_invn[v] = inv;
        #pragma unroll
        for (int i = 0; i < 4; ++i) {
            __nv_bfloat16 hi[4];
            hi[0] = __float2bfloat16(vals[i].x * inv);
            hi[1] = __float2bfloat16(vals[i].y * inv);
            hi[2] = __float2bfloat16(vals[i].z * inv);
            hi[3] = __float2bfloat16(vals[i].w * inv);
            int idx = (lane + i * 32) * 4;
            *(uint2*)&g_B16[(size_t)v * T_DIM + idx] = *(uint2*)hi;
        }
    }
}

// ---------------- K2: pass1 — bf16 GEMM, bf16 scores + tile maxima ---------------
__device__ __forceinline__ void fill_stage(uint32_t stg, int m0, int n0, int kt, int tid) {
    int kk = kt * 32;
    #pragma unroll
    for (int i = 0; i < 4; ++i) {
        int c = tid + i * 128;
        int r = c >> 2, cc = c & 3;
        cpa16(stg + swz64(r * 64 + cc * 16),
              &g_A16[(size_t)(m0 + r) * T_DIM + kk + cc * 8]);
    }
    #pragma unroll
    for (int i = 0; i < 4; ++i) {
        int c = tid + i * 128;
        int r = c >> 2, cc = c & 3;
        cpa16(stg + A_STG + swz64(r * 64 + cc * 16),
              &g_B16[(size_t)(n0 + r) * T_DIM + kk + cc * 8]);
    }
    asm volatile("cp.async.commit_group;" ::: "memory");
}

__global__ __launch_bounds__(128, 2) void k_pass1() {
    extern __shared__ __align__(16) char smraw[];
    uint32_t sm0 = (sptr(smraw) + 1023) & ~1023u;
    int tid = threadIdx.x;
    int lane = tid & 31, wid = tid >> 5;
    int warp_m = wid & 1, warp_n = wid >> 1;
    int m0 = blockIdx.x * BM;
    int n0 = blockIdx.y * BN;

    float acc[4][8][4];
    #pragma unroll
    for (int i = 0; i < 4; ++i)
        #pragma unroll
        for (int j = 0; j < 8; ++j)
            #pragma unroll
            for (int k = 0; k < 4; ++k) acc[i][j][k] = 0.f;

    #pragma unroll
    for (int p = 0; p < NSTAGE - 1; ++p)
        fill_stage(sm0 + p * STG_BYTES, m0, n0, p, tid);

    int aRow = warp_m * 64 + (lane & 15);
    int aHi  = ((lane >> 4) & 1) * 16;
    int bRow = warp_n * 64 + ((lane >> 4) & 1) * 8 + (lane & 7);
    int bHi  = ((lane >> 3) & 1) * 16;

    for (int kt = 0; kt < NKT; ++kt) {
        asm volatile("cp.async.wait_group 2;" ::: "memory");
        __syncthreads();                          // RAW(stage kt) + WAR(fill below)
        int fk = kt + NSTAGE - 1;
        if (fk < NKT) {
            fill_stage(sm0 + (fk & 3) * STG_BYTES, m0, n0, fk, tid);
        } else {
            asm volatile("cp.async.commit_group;" ::: "memory");  // keep count exact
        }

        uint32_t Ab = sm0 + (kt & 3) * STG_BYTES;
        uint32_t Bb = Ab + A_STG;
        #pragma unroll
        for (int half = 0; half < 2; ++half) {
            uint32_t a[4][4], b[4][4];
            #pragma unroll
            for (int mb = 0; mb < 4; ++mb)
                ldsm4(a[mb][0], a[mb][1], a[mb][2], a[mb][3],
                      Ab + swz64((aRow + mb * 16) * 64 + half * 32 + aHi));
            #pragma unroll
            for (int nbb = 0; nbb < 4; ++nbb)
                ldsm4(b[nbb][0], b[nbb][1], b[nbb][2], b[nbb][3],
                      Bb + swz64((bRow + nbb * 16) * 64 + half * 32 + bHi));
            #pragma unroll
            for (int mb = 0; mb < 4; ++mb)
                #pragma unroll
                for (int nbb = 0; nbb < 4; ++nbb) {
                    mma16816(acc[mb][2 * nbb],     a[mb], b[nbb][0], b[nbb][1]);
                    mma16816(acc[mb][2 * nbb + 1], a[mb], b[nbb][2], b[nbb][3]);
                }
        }
    }
    asm volatile("cp.async.wait_group 0;" ::: "memory");
    __syncthreads();                              // smem reused by epilogue

    // epilogue: bf16 score store + per-(row, tile) max + global hi-max
    float* red = (float*)smraw;                   // [128][2]
    #pragma unroll
    for (int mb = 0; mb < 4; ++mb) {
        #pragma unroll
        for (int half = 0; half < 2; ++half) {
            int row_l = warp_m * 64 + mb * 16 + half * 8 + (lane >> 2);
            int row = m0 + row_l;
            float bs = -3.0e38f;
            #pragma unroll
            for (int nb = 0; nb < 8; ++nb) {
                float2 s = make_float2(acc[mb][nb][half * 2],
                                       acc[mb][nb][half * 2 + 1]);
                __nv_bfloat162 h = __float22bfloat162_rn(s);
                *(__nv_bfloat162*)&g_s16[(size_t)row * V_SZ + n0 + warp_n * 64 +
                                         nb * 8 + (lane & 3) * 2] = h;
                bs = fmaxf(bs, fmaxf(__bfloat162float(h.x), __bfloat162float(h.y)));
            }
            #pragma unroll
            for (int o = 1; o <= 2; o <<= 1)
                bs = fmaxf(bs, __shfl_xor_sync(0xffffffffu, bs, o));
            if ((lane & 3) == 0) red[row_l * 2 + warp_n] = bs;
        }
    }
    __syncthreads();
    if (tid < 128) {
        float tm = fmaxf(red[tid * 2], red[tid * 2 + 1]);
        g_tilemax[(size_t)(m0 + tid) * NTILE + blockIdx.y] = tm;
        atomicMax(&g_hikey[m0 + tid], fkey(tm));
    }
}

// ---------------- K3: pass2 — prune -> exact rescore -> gather ------------------
__global__ __launch_bounds__(128) void k_pass2(const float* __restrict__ emb,
                                               float* __restrict__ out) {
    int m = blockIdx.x;
    int tid = threadIdx.x, wid = tid >> 5, lane = tid & 31;
    __shared__ int s_tcnt, s_ccnt;
    __shared__ float s_thr;
    __shared__ float s_red[4];
    __shared__ short s_tiles[NTILE];
    __shared__ int s_cand[256];
    const float4* kr = (const float4*)(g_kw + (size_t)m * T_DIM);

    {   // ||kw_m||^2, threshold, init
        float4 a = kr[tid];
        float ss = a.x * a.x + a.y * a.y + a.z * a.z + a.w * a.w;
        #pragma unroll
        for (int o = 16; o; o >>= 1) ss += __shfl_xor_sync(0xffffffffu, ss, o);
        if (lane == 0) s_red[wid] = ss;
        if (tid == 0) { s_tcnt = 0; s_ccnt = 0; g_best[m] = 0ull; }
    }
    __syncthreads();
    if (tid == 0) {
        float nrm = sqrtf(s_red[0] + s_red[1] + s_red[2] + s_red[3]);
        s_thr = unfkey(g_hikey[m]) - 0.013f * nrm;
    }
    __syncthreads();
    float thr = s_thr;

    for (int t = tid; t < NTILE; t += 128)
        if (g_tilemax[(size_t)m * NTILE + t] >= thr) {
            int s = atomicAdd(&s_tcnt, 1);
            s_tiles[s] = (short)t;
        }
    __syncthreads();

    int ntl = s_tcnt;
    for (int i = 0; i < ntl; ++i) {
        int v = (int)s_tiles[i] * 128 + tid;
        float sv = __bfloat162float(g_s16[(size_t)m * V_SZ + v]);
        if (sv >= thr) {
            int s = atomicAdd(&s_ccnt, 1);
            if (s < 256) s_cand[s] = v;
            else {                                 // overflow fallback (rare)
                const float4* er = (const float4*)(emb + (size_t)v * T_DIM);
                float d = 0.f;
                for (int q = 0; q < 128; ++q) {
                    float4 a = kr[q], bb = er[q];
                    d = fmaf(a.x, bb.x, d); d = fmaf(a.y, bb.y, d);
                    d = fmaf(a.z, bb.z, d); d = fmaf(a.w, bb.w, d);
                }
                float ex = d * g_invn[v];
                unsigned long long pk = ((unsigned long long)fkey(ex) << 32) |
                                        (0xFFFFFFFFu - (unsigned)v);
                atomicMax(&g_best[m], pk);
            }
        }
    }
    __syncthreads();

    int nc = min(s_ccnt, 256);
    for (int c = wid; c < nc; c += 4) {
        int v = s_cand[c];
        const float4* er = (const float4*)(emb + (size_t)v * T_DIM);
        float d = warp_dot(kr, er, lane);
        if (lane == 0) {
            float ex = d * g_invn[v];
            unsigned long long pk = ((unsigned long long)fkey(ex) << 32) |
                                    (0xFFFFFFFFu - (unsigned)v);
            atomicMax(&g_best[m], pk);
        }
    }
    __syncthreads();

    unsigned v = 0xFFFFFFFFu - (unsigned)(g_best[m] & 0xFFFFFFFFull);
    ((float4*)(out + (size_t)m * T_DIM))[tid] =
        ((const float4*)(emb + (size_t)v * T_DIM))[tid];
}

// ---------------- launcher --------------------------------------------------------
extern "C" void kernel_launch(void* const* d_in, const int* in_sizes, int n_in,
                              void* d_out, int out_size) {
    const float* audio = (const float*)d_in[0];
    const float* W     = (const float*)d_in[1];
    const float* b     = (const float*)d_in[2];
    const float* emb   = (const float*)d_in[3];
    float* out         = (float*)d_out;

    cudaFuncSetAttribute(k_pass1, cudaFuncAttributeMaxDynamicSharedMemorySize, DSMEM);

    k_prep<<<PROJ_BLKS + V_SZ / 8, 256>>>(audio, W, b, emb);
    dim3 g3(M_KW / BM, V_SZ / BN);       // (4, 386)
    k_pass1<<<g3, 128, DSMEM>>>();
    k_pass2<<<M_KW, 128>>>(emb, out);
}

// round 14
// speedup vs baseline: 1.1097x; 1.0357x over previous
#include <cuda_runtime.h>
#include <cuda_bf16.h>
#include <cstdint>

#define M_KW 512
#define K_D  768
#define T_DIM 512
#define V_SZ 49408
#define NTILE (V_SZ / 128)         // 386
#define EPSF 1e-8f

// pass-1 GEMM tiling: BK=64 (128B smem rows), 3 stages, 8 k-iterations
#define BM 128
#define BN 128
#define BK 64
#define NKT (T_DIM / BK)           // 8
#define NSTAGE 3
#define A_STG (BM * 128)           // 16384
#define B_STG (BN * 128)           // 16384
#define STG_BYTES (A_STG + B_STG)  // 32768
#define DSMEM (NSTAGE * STG_BYTES + 1024)   // 99328; x2 CTA = 194KB <= 227KB

#define PROJ_BLKS 64               // R8-proven proj config

// ---------------- device scratch ------------------------------------------------
__device__ float g_kw[M_KW * T_DIM];                       // fp32 projected keywords
__device__ __nv_bfloat16 g_A16[M_KW * T_DIM];              // bf16 of g_kw
__device__ __nv_bfloat16 g_B16[(size_t)V_SZ * T_DIM];      // bf16 normalized emb
__device__ float g_invn[V_SZ];                             // 1/max(||emb_v||,eps)
__device__ __nv_bfloat16 g_s16[(size_t)M_KW * V_SZ];       // bf16 scores (50 MB)
__device__ float g_tilemax[(size_t)M_KW * NTILE];          // per-row per-tile max
__device__ unsigned g_hikey[M_KW];                         // fkey(max bf16 score)
__device__ unsigned long long g_best[M_KW];                // packed exact argmax

// ---------------- helpers -------------------------------------------------------
__device__ __forceinline__ uint32_t sptr(const void* p) {
    return (uint32_t)__cvta_generic_to_shared(p);
}
__device__ __forceinline__ unsigned fkey(float s) {
    unsigned u = __float_as_uint(s);
    return (u & 0x80000000u) ? ~u : (u | 0x80000000u);
}
__device__ __forceinline__ float unfkey(unsigned k) {
    return (k & 0x80000000u) ? __uint_as_float(k ^ 0x80000000u) : __uint_as_float(~k);
}
__device__ __forceinline__ uint32_t swz128(uint32_t off) {  // SW128 for 128B rows
    return off ^ ((off >> 3) & 0x70);
}
__device__ __forceinline__ void cpa16(uint32_t dst, const void* src) {
    asm volatile("cp.async.cg.shared.global [%0], [%1], 16;" :: "r"(dst), "l"(src));
}
__device__ __forceinline__ void ldsm4(uint32_t& r0, uint32_t& r1, uint32_t& r2,
                                      uint32_t& r3, uint32_t addr) {
    asm volatile("ldmatrix.sync.aligned.m8n8.x4.shared.b16 {%0,%1,%2,%3}, [%4];"
                 : "=r"(r0), "=r"(r1), "=r"(r2), "=r"(r3) : "r"(addr));
}
__device__ __forceinline__ void mma16816(float* c, const uint32_t* a,
                                         uint32_t b0, uint32_t b1) {
    asm volatile(
        "mma.sync.aligned.m16n8k16.row.col.f32.bf16.bf16.f32 "
        "{%0,%1,%2,%3}, {%4,%5,%6,%7}, {%8,%9}, {%0,%1,%2,%3};"
        : "+f"(c[0]), "+f"(c[1]), "+f"(c[2]), "+f"(c[3])
        : "r"(a[0]), "r"(a[1]), "r"(a[2]), "r"(a[3]), "r"(b0), "r"(b1));
}
__device__ __forceinline__ float warp_dot(const float4* kr, const float4* er, int lane) {
    float d0 = 0.f, d1 = 0.f;
    #pragma unroll
    for (int i = 0; i < 4; i += 2) {
        float4 a0 = kr[lane + i * 32],       b0 = er[lane + i * 32];
        float4 a1 = kr[lane + (i + 1) * 32], b1 = er[lane + (i + 1) * 32];
        d0 = fmaf(a0.x, b0.x, d0); d0 = fmaf(a0.y, b0.y, d0);
        d0 = fmaf(a0.z, b0.z, d0); d0 = fmaf(a0.w, b0.w, d0);
        d1 = fmaf(a1.x, b1.x, d1); d1 = fmaf(a1.y, b1.y, d1);
        d1 = fmaf(a1.z, b1.z, d1); d1 = fmaf(a1.w, b1.w, d1);
    }
    float d = d0 + d1;
    #pragma unroll
    for (int o = 16; o; o >>= 1) d += __shfl_xor_sync(0xffffffffu, d, o);
    return d;
}

// ---------------- K1: fused prep (exact R8, measured 34.6us) ---------------------
__global__ __launch_bounds__(256) void k_prep(const float* __restrict__ A,
                                              const float* __restrict__ W,
                                              const float* __restrict__ bias,
                                              const float* __restrict__ emb) {
    __shared__ __align__(16) float As[2][64][36];
    __shared__ __align__(16) float Ws[2][32][68];
    int tid = threadIdx.x;

    if (blockIdx.x < PROJ_BLKS) {
        if (blockIdx.x == 0) { g_hikey[tid] = 0u; g_hikey[tid + 256] = 0u; }
        int m0 = (blockIdx.x >> 3) * 64;
        int n0 = (blockIdx.x & 7) * 64;
        int tx = tid & 15, ty = tid >> 4;

        {   // prologue: stage 0
            #pragma unroll
            for (int i = 0; i < 2; ++i) {
                int c = tid + i * 256;
                int m = c >> 3, kq = (c & 7) * 4;
                cpa16(sptr(&As[0][m][kq]), &A[(size_t)(m0 + m) * K_D + kq]);
            }
            #pragma unroll
            for (int i = 0; i < 2; ++i) {
                int c = tid + i * 256;
                int kk = c >> 4, nq = (c & 15) * 4;
                cpa16(sptr(&Ws[0][kk][nq]), &W[(size_t)kk * T_DIM + n0 + nq]);
            }
            asm volatile("cp.async.commit_group;" ::: "memory");
        }

        float acc[4][4] = {};
        const int NPT = K_D / 32;                  // 24
        for (int kt = 0; kt < NPT; ++kt) {
            int s = kt & 1;
            if (kt + 1 < NPT) {
                int k0 = (kt + 1) * 32, ns = s ^ 1;
                #pragma unroll
                for (int i = 0; i < 2; ++i) {
                    int c = tid + i * 256;
                    int m = c >> 3, kq = (c & 7) * 4;
                    cpa16(sptr(&As[ns][m][kq]), &A[(size_t)(m0 + m) * K_D + k0 + kq]);
                }
                #pragma unroll
                for (int i = 0; i < 2; ++i) {
                    int c = tid + i * 256;
                    int kk = c >> 4, nq = (c & 15) * 4;
                    cpa16(sptr(&Ws[ns][kk][nq]), &W[(size_t)(k0 + kk) * T_DIM + n0 + nq]);
                }
                asm volatile("cp.async.commit_group;" ::: "memory");
                asm volatile("cp.async.wait_group 1;" ::: "memory");
            } else {
                asm volatile("cp.async.wait_group 0;" ::: "memory");
            }
            __syncthreads();
            #pragma unroll
            for (int kg = 0; kg < 8; ++kg) {
                float4 av[4], bv[4];
                #pragma unroll
                for (int i = 0; i < 4; ++i)
                    av[i] = *(const float4*)&As[s][ty * 4 + i][kg * 4];
                #pragma unroll
                for (int k = 0; k < 4; ++k)
                    bv[k] = *(const float4*)&Ws[s][kg * 4 + k][tx * 4];
                #pragma unroll
                for (int i = 0; i < 4; ++i) {
                    acc[i][0] = fmaf(av[i].x, bv[0].x, acc[i][0]);
                    acc[i][1] = fmaf(av[i].x, bv[0].y, acc[i][1]);
                    acc[i][2] = fmaf(av[i].x, bv[0].z, acc[i][2]);
                    acc[i][3] = fmaf(av[i].x, bv[0].w, acc[i][3]);
                    acc[i][0] = fmaf(av[i].y, bv[1].x, acc[i][0]);
                    acc[i][1] = fmaf(av[i].y, bv[1].y, acc[i][1]);
                    acc[i][2] = fmaf(av[i].y, bv[1].z, acc[i][2]);
                    acc[i][3] = fmaf(av[i].y, bv[1].w, acc[i][3]);
                    acc[i][0] = fmaf(av[i].z, bv[2].x, acc[i][0]);
                    acc[i][1] = fmaf(av[i].z, bv[2].y, acc[i][1]);
                    acc[i][2] = fmaf(av[i].z, bv[2].z, acc[i][2]);
                    acc[i][3] = fmaf(av[i].z, bv[2].w, acc[i][3]);
                    acc[i][0] = fmaf(av[i].w, bv[3].x, acc[i][0]);
                    acc[i][1] = fmaf(av[i].w, bv[3].y, acc[i][1]);
                    acc[i][2] = fmaf(av[i].w, bv[3].z, acc[i][2]);
                    acc[i][3] = fmaf(av[i].w, bv[3].w, acc[i][3]);
                }
            }
            __syncthreads();
        }
        float4 bb = *(const float4*)&bias[n0 + tx * 4];
        #pragma unroll
        for (int i = 0; i < 4; ++i) {
            int m = m0 + ty * 4 + i;
            int n = n0 + tx * 4;
            float x[4] = {acc[i][0] + bb.x, acc[i][1] + bb.y,
                          acc[i][2] + bb.z, acc[i][3] + bb.w};
            *(float4*)&g_kw[(size_t)m * T_DIM + n] = *(float4*)x;
            __nv_bfloat16 hi[4] = {__float2bfloat16(x[0]), __float2bfloat16(x[1]),
                                   __float2bfloat16(x[2]), __float2bfloat16(x[3])};
            *(uint2*)&g_A16[(size_t)m * T_DIM + n] = *(uint2*)hi;
        }
    } else {
        int v = (blockIdx.x - PROJ_BLKS) * 8 + (tid >> 5);
        int lane = tid & 31;
        const float4* p = (const float4*)(emb + (size_t)v * T_DIM);
        float4 vals[4];
        float ss = 0.f;
        #pragma unroll
        for (int i = 0; i < 4; ++i) {
            vals[i] = p[lane + i * 32];
            ss += vals[i].x * vals[i].x + vals[i].y * vals[i].y
                + vals[i].z * vals[i].z + vals[i].w * vals[i].w;
        }
        #pragma unroll
        for (int o = 16; o; o >>= 1) ss += __shfl_xor_sync(0xffffffffu, ss, o);
        float inv = 1.0f / fmaxf(sqrtf(ss), EPSF);
        if (lane == 0) g_invn[v] = inv;
        #pragma unroll
        for (int i = 0; i < 4; ++i) {
            __nv_bfloat16 hi[4];
            hi[0] = __float2bfloat16(vals[i].x * inv);
            hi[1] = __float2bfloat16(vals[i].y * inv);
            hi[2] = __float2bfloat16(vals[i].z * inv);
            hi[3] = __float2bfloat16(vals[i].w * inv);
            int idx = (lane + i * 32) * 4;
            *(uint2*)&g_B16[(size_t)v * T_DIM + idx] = *(uint2*)hi;
        }
    }
}

// ---------------- K2: pass1 — BK=64, SW128, 3-stage, 8 iterations ----------------
__device__ __forceinline__ void fill_stage(uint32_t stg, int m0, int n0, int kt, int tid) {
    int kk = kt * BK;
    #pragma unroll
    for (int i = 0; i < 8; ++i) {                  // A: 1024 16B-chunks
        int c = tid + i * 128;
        int r = c >> 3, cc = c & 7;
        cpa16(stg + swz128(r * 128 + cc * 16),
              &g_A16[(size_t)(m0 + r) * T_DIM + kk + cc * 8]);
    }
    #pragma unroll
    for (int i = 0; i < 8; ++i) {                  // B: 1024 16B-chunks
        int c = tid + i * 128;
        int r = c >> 3, cc = c & 7;
        cpa16(stg + A_STG + swz128(r * 128 + cc * 16),
              &g_B16[(size_t)(n0 + r) * T_DIM + kk + cc * 8]);
    }
    asm volatile("cp.async.commit_group;" ::: "memory");
}

__global__ __launch_bounds__(128, 2) void k_pass1() {
    extern __shared__ __align__(16) char smraw[];
    uint32_t sm0 = (sptr(smraw) + 1023) & ~1023u;
    int tid = threadIdx.x;
    int lane = tid & 31, wid = tid >> 5;
    int warp_m = wid & 1, warp_n = wid >> 1;
    int m0 = blockIdx.x * BM;
    int n0 = blockIdx.y * BN;

    float acc[4][8][4];
    #pragma unroll
    for (int i = 0; i < 4; ++i)
        #pragma unroll
        for (int j = 0; j < 8; ++j)
            #pragma unroll
            for (int k = 0; k < 4; ++k) acc[i][j][k] = 0.f;

    #pragma unroll
    for (int p = 0; p < NSTAGE - 1; ++p)           // stages 0,1
        fill_stage(sm0 + p * STG_BYTES, m0, n0, p, tid);

    int aRow = warp_m * 64 + (lane & 15);
    int aHi  = ((lane >> 4) & 1) * 16;
    int bRow = warp_n * 64 + ((lane >> 4) & 1) * 8 + (lane & 7);
    int bHi  = ((lane >> 3) & 1) * 16;

    for (int kt = 0; kt < NKT; ++kt) {
        asm volatile("cp.async.wait_group 1;" ::: "memory");   // stage kt provably done
        __syncthreads();                           // RAW(stage kt) + WAR(fill below)
        int fk = kt + NSTAGE - 1;                  // kt + 2
        if (fk < NKT) {
            fill_stage(sm0 + (fk % NSTAGE) * STG_BYTES, m0, n0, fk, tid);
        } else {
            asm volatile("cp.async.commit_group;" ::: "memory");  // keep count exact
        }

        uint32_t Ab = sm0 + (kt % NSTAGE) * STG_BYTES;
        uint32_t Bb = Ab + A_STG;
        #pragma unroll
        for (int q = 0; q < 4; ++q) {              // 4 k-quarters of 16
            uint32_t a[4][4], b[4][4];
            #pragma unroll
            for (int mb = 0; mb < 4; ++mb)
                ldsm4(a[mb][0], a[mb][1], a[mb][2], a[mb][3],
                      Ab + swz128((aRow + mb * 16) * 128 + q * 32 + aHi));
            #pragma unroll
            for (int nbb = 0; nbb < 4; ++nbb)
                ldsm4(b[nbb][0], b[nbb][1], b[nbb][2], b[nbb][3],
                      Bb + swz128((bRow + nbb * 16) * 128 + q * 32 + bHi));
            #pragma unroll
            for (int mb = 0; mb < 4; ++mb)
                #pragma unroll
                for (int nbb = 0; nbb < 4; ++nbb) {
                    mma16816(acc[mb][2 * nbb],     a[mb], b[nbb][0], b[nbb][1]);
                    mma16816(acc[mb][2 * nbb + 1], a[mb], b[nbb][2], b[nbb][3]);
                }
        }
    }
    asm volatile("cp.async.wait_group 0;" ::: "memory");
    __syncthreads();                               // smem reused by epilogue

    // epilogue: bf16 score store + per-(row, tile) max + global hi-max
    float* red = (float*)smraw;                    // [128][2]
    #pragma unroll
    for (int mb = 0; mb < 4; ++mb) {
        #pragma unroll
        for (int half = 0; half < 2; ++half) {
            int row_l = warp_m * 64 + mb * 16 + half * 8 + (lane >> 2);
            int row = m0 + row_l;
            float bs = -3.0e38f;
            #pragma unroll
            for (int nb = 0; nb < 8; ++nb) {
                float2 s = make_float2(acc[mb][nb][half * 2],
                                       acc[mb][nb][half * 2 + 1]);
                __nv_bfloat162 h = __float22bfloat162_rn(s);
                *(__nv_bfloat162*)&g_s16[(size_t)row * V_SZ + n0 + warp_n * 64 +
                                         nb * 8 + (lane & 3) * 2] = h;
                bs = fmaxf(bs, fmaxf(__bfloat162float(h.x), __bfloat162float(h.y)));
            }
            #pragma unroll
            for (int o = 1; o <= 2; o <<= 1)
                bs = fmaxf(bs, __shfl_xor_sync(0xffffffffu, bs, o));
            if ((lane & 3) == 0) red[row_l * 2 + warp_n] = bs;
        }
    }
    __syncthreads();
    if (tid < 128) {
        float tm = fmaxf(red[tid * 2], red[tid * 2 + 1]);
        g_tilemax[(size_t)(m0 + tid) * NTILE + blockIdx.y] = tm;
        atomicMax(&g_hikey[m0 + tid], fkey(tm));
    }
}

// ---------------- K3: pass2 — prune -> exact rescore -> gather ------------------
__global__ __launch_bounds__(128) void k_pass2(const float* __restrict__ emb,
                                               float* __restrict__ out) {
    int m = blockIdx.x;
    int tid = threadIdx.x, wid = tid >> 5, lane = tid & 31;
    __shared__ int s_tcnt, s_ccnt;
    __shared__ float s_thr;
    __shared__ float s_red[4];
    __shared__ short s_tiles[NTILE];
    __shared__ int s_cand[256];
    const float4* kr = (const float4*)(g_kw + (size_t)m * T_DIM);

    {   // ||kw_m||^2, threshold, init
        float4 a = kr[tid];
        float ss = a.x * a.x + a.y * a.y + a.z * a.z + a.w * a.w;
        #pragma unroll
        for (int o = 16; o; o >>= 1) ss += __shfl_xor_sync(0xffffffffu, ss, o);
        if (lane == 0) s_red[wid] = ss;
        if (tid == 0) { s_tcnt = 0; s_ccnt = 0; g_best[m] = 0ull; }
    }
    __syncthreads();
    if (tid == 0) {
        float nrm = sqrtf(s_red[0] + s_red[1] + s_red[2] + s_red[3]);
        s_thr = unfkey(g_hikey[m]) - 0.013f * nrm;
    }
    __syncthreads();
    float thr = s_thr;

    for (int t = tid; t < NTILE; t += 128)
        if (g_tilemax[(size_t)m * NTILE + t] >= thr) {
            int s = atomicAdd(&s_tcnt, 1);
            s_tiles[s] = (short)t;
        }
    __syncthreads();

    int ntl = s_tcnt;
    for (int i = 0; i < ntl; ++i) {
        int v = (int)s_tiles[i] * 128 + tid;
        float sv = __bfloat162float(g_s16[(size_t)m * V_SZ + v]);
        if (sv >= thr) {
            int s = atomicAdd(&s_ccnt, 1);
            if (s < 256) s_cand[s] = v;
            else {                                 // overflow fallback (rare)
                const float4* er = (const float4*)(emb + (size_t)v * T_DIM);
                float d = 0.f;
                for (int q = 0; q < 128; ++q) {
                    float4 a = kr[q], bb = er[q];
                    d = fmaf(a.x, bb.x, d); d = fmaf(a.y, bb.y, d);
                    d = fmaf(a.z, bb.z, d); d = fmaf(a.w, bb.w, d);
                }
                float ex = d * g_invn[v];
                unsigned long long pk = ((unsigned long long)fkey(ex) << 32) |
                                        (0xFFFFFFFFu - (unsigned)v);
                atomicMax(&g_best[m], pk);
            }
        }
    }
    __syncthreads();

    int nc = min(s_ccnt, 256);
    for (int c = wid; c < nc; c += 4) {
        int v = s_cand[c];
        const float4* er = (const float4*)(emb + (size_t)v * T_DIM);
        float d = warp_dot(kr, er, lane);
        if (lane == 0) {
            float ex = d * g_invn[v];
            unsigned long long pk = ((unsigned long long)fkey(ex) << 32) |
                                    (0xFFFFFFFFu - (unsigned)v);
            atomicMax(&g_best[m], pk);
        }
    }
    __syncthreads();

    unsigned v = 0xFFFFFFFFu - (unsigned)(g_best[m] & 0xFFFFFFFFull);
    ((float4*)(out + (size_t)m * T_DIM))[tid] =
        ((const float4*)(emb + (size_t)v * T_DIM))[tid];
}

// ---------------- launcher --------------------------------------------------------
extern "C" void kernel_launch(void* const* d_in, const int* in_sizes, int n_in,
                              void* d_out, int out_size) {
    const float* audio = (const float*)d_in[0];
    const float* W     = (const float*)d_in[1];
    const float* b     = (const float*)d_in[2];
    const float* emb   = (const float*)d_in[3];
    float* out         = (float*)d_out;

    cudaFuncSetAttribute(k_pass1, cudaFuncAttributeMaxDynamicSharedMemorySize, DSMEM);

    k_prep<<<PROJ_BLKS + V_SZ / 8, 256>>>(audio, W, b, emb);
    dim3 g3(M_KW / BM, V_SZ / BN);       // (4, 386)
    k_pass1<<<g3, 128, DSMEM>>>();
    k_pass2<<<M_KW, 128>>>(emb, out);
}